// round 7
// baseline (speedup 1.0000x reference)
#include <cuda_runtime.h>
#include <cstdint>

#define DI __device__ __forceinline__

static constexpr int HDIM   = 1024;
static constexpr int BATCH  = 8192;
static constexpr int BM     = 128;   // batch rows per CTA
static constexpr int BN     = 32;    // gate cols per CTA (x6 gate blocks)
static constexpr int NTH    = 256;   // 8 warps: 4 (m) x 2 (n)
static constexpr int NSTAGE = 96;    // 32 input + 32 hx + 32 att K-stages
static constexpr int RING   = 3;     // 3-deep ring -> ~96KB -> 2 CTAs/SM

// stage buffer: A 128x32 tf32 (16KB) + B 4x32x32 (16KB)
static constexpr int ABYTES = BM * 128;        // 16384
static constexpr int BUFB   = ABYTES + 16384;  // 32768
static constexpr int MBOFF  = RING * BUFB;     // 98304: full[3] then empty[3]
static constexpr int SMEMB  = MBOFF + 64;      // 98368

// tf32-converted scratch (prepass output). Offsets in u32 elements.
static constexpr size_t OFF_INP  = 0;
static constexpr size_t OFF_HX   = 8388608;
static constexpr size_t OFF_ATT  = 16777216;
static constexpr size_t OFF_WIH  = 25165824;
static constexpr size_t OFF_WHH  = 29360128;
static constexpr size_t OFF_WATT = 33554432;
static constexpr size_t CVT_TOTAL = 35651584;   // ~142.6 MB

__device__ uint32_t g_cvt[CVT_TOTAL];

DI uint32_t f2tf(float x) {  // round-to-nearest tf32 (unbiased)
    uint32_t r;
    asm("cvt.rna.tf32.f32 %0, %1;" : "=r"(r) : "f"(x));
    return r;
}
DI float sigmf(float x) { return 1.0f / (1.0f + __expf(-x)); }

DI uint32_t smem_u32(const void* p) {
    uint32_t r;
    asm("{ .reg .u64 t; cvta.to.shared.u64 t, %1; cvt.u32.u64 %0, t; }" : "=r"(r) : "l"(p));
    return r;
}
DI void cp16(uint32_t sdst, const uint32_t* gsrc) {
    asm volatile("cp.async.cg.shared.global [%0], [%1], 16;" :: "r"(sdst), "l"(gsrc));
}
DI void cp_arrive(uint32_t mbar) {   // this thread's prior cp.asyncs arrive on mbar
    asm volatile("cp.async.mbarrier.arrive.noinc.shared.b64 [%0];" :: "r"(mbar) : "memory");
}
DI void mbar_init(uint32_t a, uint32_t cnt) {
    asm volatile("mbarrier.init.shared.b64 [%0], %1;" :: "r"(a), "r"(cnt) : "memory");
}
DI void mbar_arrive(uint32_t a) {
    asm volatile("mbarrier.arrive.shared.b64 _, [%0];" :: "r"(a) : "memory");
}
DI void mbar_wait(uint32_t a, uint32_t parity) {
    asm volatile(
        "{\n\t.reg .pred P;\n"
        "W%=:\n\t"
        "mbarrier.try_wait.parity.acquire.cta.shared::cta.b64 P, [%0], %1, 0x989680;\n\t"
        "@!P bra W%=;\n\t}"
        :: "r"(a), "r"(parity) : "memory");
}

DI void ldsm4(uint32_t* r, uint32_t addr) {
    asm volatile("ldmatrix.sync.aligned.m8n8.x4.shared.b16 {%0,%1,%2,%3}, [%4];"
                 : "=r"(r[0]), "=r"(r[1]), "=r"(r[2]), "=r"(r[3]) : "r"(addr));
}
DI void mma8(float* d, const uint32_t* a, const uint32_t* b) {
    asm volatile(
        "mma.sync.aligned.m16n8k8.row.col.f32.tf32.tf32.f32 "
        "{%0,%1,%2,%3}, {%4,%5,%6,%7}, {%8,%9}, {%0,%1,%2,%3};"
        : "+f"(d[0]), "+f"(d[1]), "+f"(d[2]), "+f"(d[3])
        : "r"(a[0]), "r"(a[1]), "r"(a[2]), "r"(a[3]), "r"(b[0]), "r"(b[1]));
}

// ---- prepass: single launch, fp32 -> tf32(RNA) bulk convert (6 segments) ----
__global__ void cvt_all_kernel(const float4* s0, const float4* s1, const float4* s2,
                               const float4* s3, const float4* s4, const float4* s5)
{
    const int seg = blockIdx.y;
    const float4* src;
    uint4* dst;
    int n4;
    uint32_t* g = g_cvt;
    switch (seg) {
        case 0: src = s0; dst = (uint4*)(g + OFF_INP);  n4 = 2097152; break;
        case 1: src = s1; dst = (uint4*)(g + OFF_HX);   n4 = 2097152; break;
        case 2: src = s2; dst = (uint4*)(g + OFF_ATT);  n4 = 2097152; break;
        case 3: src = s3; dst = (uint4*)(g + OFF_WIH);  n4 = 1048576; break;
        case 4: src = s4; dst = (uint4*)(g + OFF_WHH);  n4 = 1048576; break;
        default: src = s5; dst = (uint4*)(g + OFF_WATT); n4 = 524288; break;
    }
    int i = blockIdx.x * blockDim.x + threadIdx.x;
    int stride = gridDim.x * blockDim.x;
    for (; i < n4; i += stride) {
        float4 v = __ldg(src + i);
        dst[i] = make_uint4(f2tf(v.x), f2tf(v.y), f2tf(v.z), f2tf(v.w));
    }
}

// ---- main kernel ----
// stages 0..31 : A=input, B=wih  (4 gate blocks, accum c[0..3])
// stages 32..63: A=hx,    B=whh  (4 gate blocks, accum c[0..3])
// stages 64..95: A=att,   B=watt (2 att blocks,  accum c[4..5])
DI void issue_stage(int s, uint32_t buf, uint32_t sA, uint32_t sB,
                    const uint32_t* Arow, const uint32_t* Brow)
{
    const int seg = s >> 5;
    const int k0  = (s & 31) << 5;
    const uint32_t* Ap = Arow + (size_t)seg * 8388608 + k0;
    const uint32_t* Bp = Brow + (size_t)seg * 4194304 + k0;
    const uint32_t dA = buf + sA;
    const uint32_t dB = buf + sB;
    cp16(dA,         Ap);
    cp16(dA + 4096,  Ap + 32768);
    cp16(dA + 8192,  Ap + 65536);
    cp16(dA + 12288, Ap + 98304);
    cp16(dB,         Bp);
    cp16(dB + 4096,  Bp + 1048576);
    if (seg != 2) {
        cp16(dB + 8192,  Bp + 2097152);
        cp16(dB + 12288, Bp + 3145728);
    }
}

template <int NB, int CB>
DI void compute_stage(uint32_t buf, uint32_t pA0, uint32_t pA1, uint32_t pB,
                      float c[6][2][2][4])
{
    const uint32_t aA0 = buf + pA0;
    const uint32_t aA1 = buf + pA1;
    const uint32_t bB  = buf + pB;
    #pragma unroll
    for (int k8 = 0; k8 < 4; ++k8) {
        const uint32_t kx = (uint32_t)(k8 << 5);   // immediate XOR per k8
        uint32_t a0[4], a1[4];
        ldsm4(a0, aA0 ^ kx);
        ldsm4(a1, aA1 ^ kx);
        #pragma unroll
        for (int blk = 0; blk < NB; ++blk) {
            uint32_t b[4];
            ldsm4(b, (bB + blk * 4096) ^ kx);
            mma8(c[CB + blk][0][0], a0, b);
            mma8(c[CB + blk][0][1], a0, b + 2);
            mma8(c[CB + blk][1][0], a1, b);
            mma8(c[CB + blk][1][1], a1, b + 2);
        }
    }
}

__global__ __launch_bounds__(NTH, 2)
void lstm_att_kernel(const float* __restrict__ cx,
                     const float* __restrict__ bih, const float* __restrict__ bhh,
                     const float* __restrict__ batt,
                     float* __restrict__ out)
{
    extern __shared__ char smem[];
    const int tid  = threadIdx.x;
    const int wid  = tid >> 5;
    const int lane = tid & 31;
    const int wm = wid >> 1, wn = wid & 1;
    const int n0 = blockIdx.x * BN;
    const int m0 = blockIdx.y * BM;
    const uint32_t sbase = smem_u32(smem);
    const uint32_t fullb  = sbase + MBOFF;       // 3 x 8B
    const uint32_t emptyb = sbase + MBOFF + 24;  // 3 x 8B

    if (tid == 0) {
        #pragma unroll
        for (int i = 0; i < RING; ++i) {
            mbar_init(fullb + i * 8, NTH);   // all threads' cp.async arrivals
            mbar_init(emptyb + i * 8, 8);    // one arrive per warp
        }
    }
    __syncthreads();

    // ---- loop-invariant producer addressing (NTH=256: blk == j-unroll index) ----
    const int tid8 = tid >> 3;           // 0..31 row within 32-row chunk
    const int cc   = tid & 7;            // 16B column
    const uint32_t sw   = (uint32_t)((cc ^ (tid8 & 7)) << 4);
    const uint32_t sAof = (uint32_t)(tid8 * 128) + sw;            // A dst offset in buf
    const uint32_t sBof = (uint32_t)ABYTES + (uint32_t)(tid8 * 128) + sw;
    const uint32_t* Arow = g_cvt + OFF_INP + (size_t)(m0 + tid8) * HDIM + cc * 4;
    const uint32_t* Brow = g_cvt + OFF_WIH + (size_t)(n0 + tid8) * HDIM + cc * 4;

    // ---- loop-invariant consumer (ldsm) addressing, XOR-folded ----
    const int rowA = wm * 32 + (lane & 15);
    const int ahi  = (lane >> 4) & 1;
    const int ax   = rowA & 7;
    const uint32_t pA0 = (uint32_t)(rowA * 128)        ^ (uint32_t)(((ahi ^ ax) & 7) << 4);
    const uint32_t pA1 = (uint32_t)((rowA + 16) * 128) ^ (uint32_t)(((ahi ^ ax) & 7) << 4);
    const int rowB = wn * 16 + (lane & 7) + ((lane & 16) >> 1);
    const int bhi  = (lane >> 3) & 1;
    const int bx   = rowB & 7;
    const uint32_t pB  = (uint32_t)ABYTES + ((uint32_t)(rowB * 128) ^ (uint32_t)(((bhi ^ bx) & 7) << 4));

    float c[6][2][2][4];
    #pragma unroll
    for (int b = 0; b < 6; ++b)
        #pragma unroll
        for (int mf = 0; mf < 2; ++mf)
            #pragma unroll
            for (int nf = 0; nf < 2; ++nf)
                #pragma unroll
                for (int i = 0; i < 4; ++i) c[b][mf][nf][i] = 0.0f;

    // prime stages 0,1 (slots initially empty; producer phase starts flipped)
    issue_stage(0, sbase,        sAof, sBof, Arow, Brow);
    cp_arrive(fullb);
    issue_stage(1, sbase + BUFB, sAof, sBof, Arow, Brow);
    cp_arrive(fullb + 8);

    int ps = 2, pp = 1;    // producer slot/phase (stages 2..95)
    int cs = 0, cph = 0;   // consumer slot/phase (stages 0..95)
    for (int s = 0; s < NSTAGE; ++s) {
        if (s + 2 < NSTAGE) {
            mbar_wait(emptyb + ps * 8, (uint32_t)pp);
            issue_stage(s + 2, sbase + ps * BUFB, sAof, sBof, Arow, Brow);
            cp_arrive(fullb + ps * 8);
            if (++ps == RING) { ps = 0; pp ^= 1; }
        }
        mbar_wait(fullb + cs * 8, (uint32_t)cph);
        const uint32_t buf = sbase + cs * BUFB;
        if (s < 64) compute_stage<4, 0>(buf, pA0, pA1, pB, c);
        else        compute_stage<2, 4>(buf, pA0, pA1, pB, c);
        if (lane == 0) mbar_arrive(emptyb + cs * 8);
        if (++cs == RING) { cs = 0; cph ^= 1; }
    }

    // ---- fused LSTM epilogue: all 6 gates for (row,col) live in this thread ----
    const int gid = lane >> 2, tig = lane & 3;
    const size_t cy_base = (size_t)BATCH * HDIM;
    #pragma unroll
    for (int mf = 0; mf < 2; ++mf) {
        #pragma unroll
        for (int i2 = 0; i2 < 2; ++i2) {
            const int row = m0 + wm * 32 + mf * 16 + gid + i2 * 8;
            #pragma unroll
            for (int nf = 0; nf < 2; ++nf) {
                const int col = n0 + wn * 16 + nf * 8 + tig * 2;
                float2 cx2 = __ldg((const float2*)(cx + (size_t)row * HDIM + col));
                float hyv[2], cyv[2];
                #pragma unroll
                for (int q = 0; q < 2; ++q) {
                    const int i = i2 * 2 + q;
                    const int n = col + q;
                    float gi  = c[0][mf][nf][i] + __ldg(bih + n)        + __ldg(bhh + n);
                    float gf  = c[1][mf][nf][i] + __ldg(bih + 1024 + n) + __ldg(bhh + 1024 + n);
                    float gc  = c[2][mf][nf][i] + __ldg(bih + 2048 + n) + __ldg(bhh + 2048 + n);
                    float go  = c[3][mf][nf][i] + __ldg(bih + 3072 + n) + __ldg(bhh + 3072 + n);
                    float gia = c[4][mf][nf][i] + __ldg(batt + n);
                    float gaa = c[5][mf][nf][i] + __ldg(batt + 1024 + n);
                    float i_  = sigmf(gi);
                    float f_  = sigmf(gf);
                    float c_  = tanhf(gc);
                    float o_  = sigmf(go);
                    float ia_ = sigmf(gia);
                    float aa_ = tanhf(gaa);
                    float cv  = f_ * ((q == 0) ? cx2.x : cx2.y) + i_ * c_ + ia_ * aa_;
                    cyv[q] = cv;
                    hyv[q] = o_ * tanhf(cv);
                }
                *(float2*)(out + (size_t)row * HDIM + col)           = make_float2(hyv[0], hyv[1]);
                *(float2*)(out + cy_base + (size_t)row * HDIM + col) = make_float2(cyv[0], cyv[1]);
            }
        }
    }
}

extern "C" void kernel_launch(void* const* d_in, const int* in_sizes, int n_in,
                              void* d_out, int out_size)
{
    (void)in_sizes; (void)n_in; (void)out_size;
    const float* inp  = (const float*)d_in[0];
    const float* hx   = (const float*)d_in[1];
    const float* cx   = (const float*)d_in[2];
    const float* att  = (const float*)d_in[3];
    const float* wih  = (const float*)d_in[4];
    const float* whh  = (const float*)d_in[5];
    const float* bih  = (const float*)d_in[6];
    const float* bhh  = (const float*)d_in[7];
    const float* watt = (const float*)d_in[8];
    const float* batt = (const float*)d_in[9];
    float* out = (float*)d_out;

    dim3 cgrid(1024, 6);
    cvt_all_kernel<<<cgrid, 256>>>((const float4*)inp, (const float4*)hx,
                                   (const float4*)att, (const float4*)wih,
                                   (const float4*)whh, (const float4*)watt);

    cudaFuncSetAttribute(lstm_att_kernel,
                         cudaFuncAttributeMaxDynamicSharedMemorySize, SMEMB);
    dim3 grid(HDIM / BN, BATCH / BM);  // n-tiles fastest => A/L2 reuse within a wave
    lstm_att_kernel<<<grid, NTH, SMEMB>>>(cx, bih, bhh, batt, out);
}

// round 8
// speedup vs baseline: 1.0388x; 1.0388x over previous
#include <cuda_runtime.h>
#include <cstdint>

#define DI __device__ __forceinline__

static constexpr int HDIM   = 1024;
static constexpr int BATCH  = 8192;
static constexpr int BM     = 128;   // batch rows per CTA
static constexpr int BN     = 32;    // gate cols per CTA
static constexpr int NTH    = 256;   // 8 warps: 4 (m) x 2 (n)
static constexpr int NSTAGE = 96;    // 32 att + 32 input + 32 hx K-stages
static constexpr int RING   = 3;     // 3-deep ring -> 96KB -> 2 CTAs/SM

static constexpr int ABYTES = BM * 128;        // 16384
static constexpr int BUFB   = ABYTES + 16384;  // 32768
static constexpr int SMEMB  = RING * BUFB;     // 98304

// tf32 scratch layout (elements): att first so its accumulators retire early
static constexpr size_t OFF_ATT  = 0;
static constexpr size_t OFF_INP  = 8388608;
static constexpr size_t OFF_HX   = 16777216;
static constexpr size_t OFF_WATT = 25165824;
static constexpr size_t OFF_WIH  = 27262976;
static constexpr size_t OFF_WHH  = 31457280;
static constexpr size_t CVT_TOTAL = 35651584;   // ~142.6 MB

__device__ uint32_t g_cvt[CVT_TOTAL];

DI uint32_t f2tf(float x) {
    uint32_t r;
    asm("cvt.rna.tf32.f32 %0, %1;" : "=r"(r) : "f"(x));
    return r;
}
DI float sigmf(float x) { return 1.0f / (1.0f + __expf(-x)); }

DI uint32_t smem_u32(const void* p) {
    uint32_t r;
    asm("{ .reg .u64 t; cvta.to.shared.u64 t, %1; cvt.u32.u64 %0, t; }" : "=r"(r) : "l"(p));
    return r;
}
DI void cp16(uint32_t sdst, const uint32_t* gsrc) {
    asm volatile("cp.async.cg.shared.global [%0], [%1], 16;" :: "r"(sdst), "l"(gsrc));
}
DI void cp_commit() { asm volatile("cp.async.commit_group;" ::: "memory"); }
template <int N>
DI void cp_wait() { asm volatile("cp.async.wait_group %0;" :: "n"(N) : "memory"); }

DI void ldsm4(uint32_t* r, uint32_t addr) {
    asm volatile("ldmatrix.sync.aligned.m8n8.x4.shared.b16 {%0,%1,%2,%3}, [%4];"
                 : "=r"(r[0]), "=r"(r[1]), "=r"(r[2]), "=r"(r[3]) : "r"(addr));
}
DI void mma8(float* d, const uint32_t* a, const uint32_t* b) {
    asm volatile(
        "mma.sync.aligned.m16n8k8.row.col.f32.tf32.tf32.f32 "
        "{%0,%1,%2,%3}, {%4,%5,%6,%7}, {%8,%9}, {%0,%1,%2,%3};"
        : "+f"(d[0]), "+f"(d[1]), "+f"(d[2]), "+f"(d[3])
        : "r"(a[0]), "r"(a[1]), "r"(a[2]), "r"(a[3]), "r"(b[0]), "r"(b[1]));
}

// ---- prepass: single launch, fp32 -> tf32(RNA) bulk convert (6 segments) ----
__global__ void cvt_all_kernel(const float4* s_att, const float4* s_inp, const float4* s_hx,
                               const float4* s_watt, const float4* s_wih, const float4* s_whh)
{
    const int seg = blockIdx.y;
    const float4* src;
    uint4* dst;
    int n4;
    uint32_t* g = g_cvt;
    switch (seg) {
        case 0: src = s_att;  dst = (uint4*)(g + OFF_ATT);  n4 = 2097152; break;
        case 1: src = s_inp;  dst = (uint4*)(g + OFF_INP);  n4 = 2097152; break;
        case 2: src = s_hx;   dst = (uint4*)(g + OFF_HX);   n4 = 2097152; break;
        case 3: src = s_watt; dst = (uint4*)(g + OFF_WATT); n4 = 524288;  break;
        case 4: src = s_wih;  dst = (uint4*)(g + OFF_WIH);  n4 = 1048576; break;
        default: src = s_whh; dst = (uint4*)(g + OFF_WHH);  n4 = 1048576; break;
    }
    int i = blockIdx.x * blockDim.x + threadIdx.x;
    int stride = gridDim.x * blockDim.x;
    for (; i < n4; i += stride) {
        float4 v = __ldg(src + i);
        dst[i] = make_uint4(f2tf(v.x), f2tf(v.y), f2tf(v.z), f2tf(v.w));
    }
}

// ---- main kernel ----
// stages 0..31 : A=att,   B=watt (2 att blocks)
// stages 32..63: A=input, B=wih  (4 gate blocks)
// stages 64..95: A=hx,    B=whh  (4 gate blocks)
DI void issue_stage(int s, uint32_t buf, uint32_t sA, uint32_t sB,
                    const uint32_t* Arow, const uint32_t* Brow)
{
    const int seg = s >> 5;
    const int k0  = (s & 31) << 5;
    const uint32_t bsel = (seg == 0) ? 0u : ((seg == 1) ? 2097152u : 6291456u);
    const uint32_t* Ap = Arow + (size_t)seg * 8388608 + k0;
    const uint32_t* Bp = Brow + bsel + k0;
    const uint32_t dA = buf + sA;
    const uint32_t dB = buf + sB;
    cp16(dA,         Ap);
    cp16(dA + 4096,  Ap + 32768);
    cp16(dA + 8192,  Ap + 65536);
    cp16(dA + 12288, Ap + 98304);
    cp16(dB,         Bp);
    cp16(dB + 4096,  Bp + 1048576);
    if (seg != 0) {
        cp16(dB + 8192,  Bp + 2097152);
        cp16(dB + 12288, Bp + 3145728);
    }
    cp_commit();
}

template <int NB>
DI void compute_stage(uint32_t buf, uint32_t pA0, uint32_t pA1, uint32_t pB,
                      float c[][2][2][4])
{
    const uint32_t aA0 = buf + pA0;
    const uint32_t aA1 = buf + pA1;
    const uint32_t bB  = buf + pB;
    #pragma unroll
    for (int k8 = 0; k8 < 4; ++k8) {
        const uint32_t kx = (uint32_t)(k8 << 5);
        uint32_t a0[4], a1[4];
        ldsm4(a0, aA0 ^ kx);
        ldsm4(a1, aA1 ^ kx);
        #pragma unroll
        for (int blk = 0; blk < NB; ++blk) {
            uint32_t b[4];
            ldsm4(b, (bB + blk * 4096) ^ kx);
            mma8(c[blk][0][0], a0, b);
            mma8(c[blk][0][1], a0, b + 2);
            mma8(c[blk][1][0], a1, b);
            mma8(c[blk][1][1], a1, b + 2);
        }
    }
}

__global__ __launch_bounds__(NTH, 2)
void lstm_att_kernel(const float* __restrict__ cx,
                     const float* __restrict__ bih, const float* __restrict__ bhh,
                     const float* __restrict__ batt,
                     float* __restrict__ out)
{
    extern __shared__ char smem[];
    const int tid  = threadIdx.x;
    const int wid  = tid >> 5;
    const int lane = tid & 31;
    const int wm = wid >> 1, wn = wid & 1;
    const int n0 = blockIdx.x * BN;
    const int m0 = blockIdx.y * BM;
    const uint32_t sbase = smem_u32(smem);

    // ---- loop-invariant producer addressing ----
    const int tid8 = tid >> 3;
    const int cc   = tid & 7;
    const uint32_t sw   = (uint32_t)((cc ^ (tid8 & 7)) << 4);
    const uint32_t sAof = (uint32_t)(tid8 * 128) + sw;
    const uint32_t sBof = (uint32_t)ABYTES + (uint32_t)(tid8 * 128) + sw;
    const uint32_t* Arow = g_cvt + OFF_ATT  + (size_t)(m0 + tid8) * HDIM + cc * 4;
    const uint32_t* Brow = g_cvt + OFF_WATT + (size_t)(n0 + tid8) * HDIM + cc * 4;

    // ---- loop-invariant consumer (ldsm) addressing, XOR-folded ----
    const int rowA = wm * 32 + (lane & 15);
    const int ahi  = (lane >> 4) & 1;
    const int ax   = rowA & 7;
    const uint32_t pA0 = (uint32_t)(rowA * 128)        ^ (uint32_t)(((ahi ^ ax) & 7) << 4);
    const uint32_t pA1 = (uint32_t)((rowA + 16) * 128) ^ (uint32_t)(((ahi ^ ax) & 7) << 4);
    const int rowB = wn * 16 + (lane & 7) + ((lane & 16) >> 1);
    const int bhi  = (lane >> 3) & 1;
    const int bx   = rowB & 7;
    const uint32_t pB  = (uint32_t)ABYTES + ((uint32_t)(rowB * 128) ^ (uint32_t)(((bhi ^ bx) & 7) << 4));

    issue_stage(0, sbase,        sAof, sBof, Arow, Brow);
    issue_stage(1, sbase + BUFB, sAof, sBof, Arow, Brow);

    int ring_c = 0, ring_i = 2;

    // ===== phase 1: att segment (stages 0..31), only 32 accum regs live =====
    float ca[2][2][2][4];
    #pragma unroll
    for (int b = 0; b < 2; ++b)
        #pragma unroll
        for (int mf = 0; mf < 2; ++mf)
            #pragma unroll
            for (int nf = 0; nf < 2; ++nf)
                #pragma unroll
                for (int i = 0; i < 4; ++i) ca[b][mf][nf][i] = 0.0f;

    for (int s = 0; s < 32; ++s) {
        cp_wait<1>();
        __syncthreads();
        issue_stage(s + 2, sbase + ring_i * BUFB, sAof, sBof, Arow, Brow);
        compute_stage<2>(sbase + ring_c * BUFB, pA0, pA1, pB, ca);
        ring_c = (ring_c == RING - 1) ? 0 : ring_c + 1;
        ring_i = (ring_i == RING - 1) ? 0 : ring_i + 1;
    }

    // ---- collapse att gates to 16 partials: p = sigmoid(ia) * tanh(aa) ----
    const int gid = lane >> 2, tig = lane & 3;
    float p[2][2][4];
    {
        float bt0[2][2], bt1[2][2];
        #pragma unroll
        for (int nf = 0; nf < 2; ++nf) {
            const int col = n0 + wn * 16 + nf * 8 + tig * 2;
            float2 t0 = __ldg((const float2*)(batt + col));
            float2 t1 = __ldg((const float2*)(batt + 1024 + col));
            bt0[nf][0] = t0.x; bt0[nf][1] = t0.y;
            bt1[nf][0] = t1.x; bt1[nf][1] = t1.y;
        }
        #pragma unroll
        for (int mf = 0; mf < 2; ++mf)
            #pragma unroll
            for (int nf = 0; nf < 2; ++nf)
                #pragma unroll
                for (int i = 0; i < 4; ++i) {
                    const int q = i & 1;
                    float ia = sigmf(ca[0][mf][nf][i] + bt0[nf][q]);
                    float aa = tanhf(ca[1][mf][nf][i] + bt1[nf][q]);
                    p[mf][nf][i] = ia * aa;
                }
    }

    // ===== phase 2: input + hx segments (stages 32..95), 64+16 accum regs =====
    float cm[4][2][2][4];
    #pragma unroll
    for (int b = 0; b < 4; ++b)
        #pragma unroll
        for (int mf = 0; mf < 2; ++mf)
            #pragma unroll
            for (int nf = 0; nf < 2; ++nf)
                #pragma unroll
                for (int i = 0; i < 4; ++i) cm[b][mf][nf][i] = 0.0f;

    for (int s = 32; s < NSTAGE; ++s) {
        cp_wait<1>();
        __syncthreads();
        if (s + 2 < NSTAGE)
            issue_stage(s + 2, sbase + ring_i * BUFB, sAof, sBof, Arow, Brow);
        else
            cp_commit();
        compute_stage<4>(sbase + ring_c * BUFB, pA0, pA1, pB, cm);
        ring_c = (ring_c == RING - 1) ? 0 : ring_c + 1;
        ring_i = (ring_i == RING - 1) ? 0 : ring_i + 1;
    }

    // ---- fused LSTM epilogue ----
    const size_t cy_base = (size_t)BATCH * HDIM;
    #pragma unroll
    for (int mf = 0; mf < 2; ++mf) {
        #pragma unroll
        for (int i2 = 0; i2 < 2; ++i2) {
            const int row = m0 + wm * 32 + mf * 16 + gid + i2 * 8;
            #pragma unroll
            for (int nf = 0; nf < 2; ++nf) {
                const int col = n0 + wn * 16 + nf * 8 + tig * 2;
                float2 cx2 = __ldg((const float2*)(cx + (size_t)row * HDIM + col));
                float hyv[2], cyv[2];
                #pragma unroll
                for (int q = 0; q < 2; ++q) {
                    const int i = i2 * 2 + q;
                    const int n = col + q;
                    float gi  = cm[0][mf][nf][i] + __ldg(bih + n)        + __ldg(bhh + n);
                    float gf  = cm[1][mf][nf][i] + __ldg(bih + 1024 + n) + __ldg(bhh + 1024 + n);
                    float gc  = cm[2][mf][nf][i] + __ldg(bih + 2048 + n) + __ldg(bhh + 2048 + n);
                    float go  = cm[3][mf][nf][i] + __ldg(bih + 3072 + n) + __ldg(bhh + 3072 + n);
                    float i_  = sigmf(gi);
                    float f_  = sigmf(gf);
                    float c_  = tanhf(gc);
                    float o_  = sigmf(go);
                    float cv  = f_ * ((q == 0) ? cx2.x : cx2.y) + i_ * c_ + p[mf][nf][i];
                    cyv[q] = cv;
                    hyv[q] = o_ * tanhf(cv);
                }
                *(float2*)(out + (size_t)row * HDIM + col)           = make_float2(hyv[0], hyv[1]);
                *(float2*)(out + cy_base + (size_t)row * HDIM + col) = make_float2(cyv[0], cyv[1]);
            }
        }
    }
}

extern "C" void kernel_launch(void* const* d_in, const int* in_sizes, int n_in,
                              void* d_out, int out_size)
{
    (void)in_sizes; (void)n_in; (void)out_size;
    const float* inp  = (const float*)d_in[0];
    const float* hx   = (const float*)d_in[1];
    const float* cx   = (const float*)d_in[2];
    const float* att  = (const float*)d_in[3];
    const float* wih  = (const float*)d_in[4];
    const float* whh  = (const float*)d_in[5];
    const float* bih  = (const float*)d_in[6];
    const float* bhh  = (const float*)d_in[7];
    const float* watt = (const float*)d_in[8];
    const float* batt = (const float*)d_in[9];
    float* out = (float*)d_out;

    dim3 cgrid(1024, 6);
    cvt_all_kernel<<<cgrid, 256>>>((const float4*)att, (const float4*)inp,
                                   (const float4*)hx,  (const float4*)watt,
                                   (const float4*)wih, (const float4*)whh);

    cudaFuncSetAttribute(lstm_att_kernel,
                         cudaFuncAttributeMaxDynamicSharedMemorySize, SMEMB);
    dim3 grid(HDIM / BN, BATCH / BM);
    lstm_att_kernel<<<grid, NTH, SMEMB>>>(cx, bih, bhh, batt, out);
}

// round 9
// speedup vs baseline: 1.6503x; 1.5886x over previous
#include <cuda_runtime.h>
#include <cuda_fp16.h>
#include <cstdint>

#define DI __device__ __forceinline__

static constexpr int HDIM   = 1024;
static constexpr int BATCH  = 8192;
static constexpr int BM     = 128;   // batch rows per CTA
static constexpr int BN     = 32;    // gate cols per CTA
static constexpr int NTH    = 256;   // 8 warps: 4 (m) x 2 (n)
static constexpr int NSTAGE = 96;    // 32 att + 32 input + 32 hx K-stages
static constexpr int RING   = 5;     // 5-deep ring, 4-stage lookahead

// fp16 stage buffer: A 128x32 (8KB) + B 4x32x32 (8KB)
static constexpr int ABYTES = BM * 64;         // 8192
static constexpr int BUFB   = ABYTES + 8192;   // 16384
static constexpr int SMEMB  = RING * BUFB;     // 81920

// fp16 scratch (u32 element offsets; 2 halves per u32)
static constexpr size_t OFF_ATT  = 0;
static constexpr size_t OFF_INP  = 4194304;
static constexpr size_t OFF_HX   = 8388608;
static constexpr size_t OFF_WATT = 12582912;
static constexpr size_t OFF_WIH  = 13631488;
static constexpr size_t OFF_WHH  = 15728640;
static constexpr size_t CVT_TOTAL = 17825792;   // ~71.3 MB

__device__ uint32_t g_cvt[CVT_TOTAL];

DI float sigmf(float x) { return 1.0f / (1.0f + __expf(-x)); }

DI uint32_t smem_u32(const void* p) {
    uint32_t r;
    asm("{ .reg .u64 t; cvta.to.shared.u64 t, %1; cvt.u32.u64 %0, t; }" : "=r"(r) : "l"(p));
    return r;
}
DI void cp16(uint32_t sdst, const uint32_t* gsrc) {
    asm volatile("cp.async.cg.shared.global [%0], [%1], 16;" :: "r"(sdst), "l"(gsrc));
}
DI void cp_commit() { asm volatile("cp.async.commit_group;" ::: "memory"); }
template <int N>
DI void cp_wait() { asm volatile("cp.async.wait_group %0;" :: "n"(N) : "memory"); }

DI void ldsm4(uint32_t* r, uint32_t addr) {
    asm volatile("ldmatrix.sync.aligned.m8n8.x4.shared.b16 {%0,%1,%2,%3}, [%4];"
                 : "=r"(r[0]), "=r"(r[1]), "=r"(r[2]), "=r"(r[3]) : "r"(addr));
}
DI void mma16(float* d, const uint32_t* a, const uint32_t* b) {
    asm volatile(
        "mma.sync.aligned.m16n8k16.row.col.f32.f16.f16.f32 "
        "{%0,%1,%2,%3}, {%4,%5,%6,%7}, {%8,%9}, {%0,%1,%2,%3};"
        : "+f"(d[0]), "+f"(d[1]), "+f"(d[2]), "+f"(d[3])
        : "r"(a[0]), "r"(a[1]), "r"(a[2]), "r"(a[3]), "r"(b[0]), "r"(b[1]));
}

// ---- prepass: fp32 -> fp16(RN) bulk convert, single launch (6 segments) ----
__global__ void cvt_all_kernel(const float4* s_att, const float4* s_inp, const float4* s_hx,
                               const float4* s_watt, const float4* s_wih, const float4* s_whh)
{
    const int seg = blockIdx.y;
    const float4* src;
    uint2* dst;
    int n4;
    uint32_t* g = g_cvt;
    switch (seg) {
        case 0: src = s_att;  dst = (uint2*)(g + OFF_ATT);  n4 = 2097152; break;
        case 1: src = s_inp;  dst = (uint2*)(g + OFF_INP);  n4 = 2097152; break;
        case 2: src = s_hx;   dst = (uint2*)(g + OFF_HX);   n4 = 2097152; break;
        case 3: src = s_watt; dst = (uint2*)(g + OFF_WATT); n4 = 524288;  break;
        case 4: src = s_wih;  dst = (uint2*)(g + OFF_WIH);  n4 = 1048576; break;
        default: src = s_whh; dst = (uint2*)(g + OFF_WHH);  n4 = 1048576; break;
    }
    int i = blockIdx.x * blockDim.x + threadIdx.x;
    int stride = gridDim.x * blockDim.x;
    for (; i < n4; i += stride) {
        float4 v = __ldg(src + i);
        __half2 lo = __float22half2_rn(make_float2(v.x, v.y));
        __half2 hi = __float22half2_rn(make_float2(v.z, v.w));
        dst[i] = make_uint2(*(const uint32_t*)&lo, *(const uint32_t*)&hi);
    }
}

// ---- main kernel ----
// stages 0..31 : A=att,   B=watt (2 att blocks)
// stages 32..63: A=input, B=wih  (4 gate blocks)
// stages 64..95: A=hx,    B=whh  (4 gate blocks)
DI void issue_stage(int s, uint32_t buf,
                    uint32_t dA0, uint32_t dB0,
                    const uint32_t* Arow, const uint32_t* Brow)
{
    const int seg = s >> 5;
    const int k   = (s & 31) << 4;                 // u32 offset within row
    const uint32_t bsel = (seg == 0) ? 0u : ((seg == 1) ? 1048576u : 3145728u);
    const uint32_t* Ap = Arow + (size_t)seg * 4194304 + k;
    const uint32_t* Bp = Brow + bsel + k;
    cp16(buf + dA0,        Ap);
    cp16(buf + dA0 + 4096, Ap + 32768);
    cp16(buf + dB0,        Bp);
    if (seg != 0)
        cp16(buf + dB0 + 4096, Bp + 1048576);
    cp_commit();
}

template <int NB>
DI void compute_stage(uint32_t buf, uint32_t pA0, uint32_t pA1, uint32_t pB,
                      float c[][2][2][4])
{
    const uint32_t aA0 = buf + pA0;
    const uint32_t aA1 = buf + pA1;
    const uint32_t bB  = buf + pB;
    #pragma unroll
    for (int k16 = 0; k16 < 2; ++k16) {
        const uint32_t kx = (uint32_t)(k16 << 5);
        uint32_t a0[4], a1[4];
        ldsm4(a0, aA0 ^ kx);
        ldsm4(a1, aA1 ^ kx);
        #pragma unroll
        for (int blk = 0; blk < NB; ++blk) {
            uint32_t b[4];
            ldsm4(b, (bB + blk * 2048) ^ kx);
            mma16(c[blk][0][0], a0, b);
            mma16(c[blk][0][1], a0, b + 2);
            mma16(c[blk][1][0], a1, b);
            mma16(c[blk][1][1], a1, b + 2);
        }
    }
}

__global__ __launch_bounds__(NTH, 2)
void lstm_att_kernel(const float* __restrict__ cx,
                     const float* __restrict__ bih, const float* __restrict__ bhh,
                     const float* __restrict__ batt,
                     float* __restrict__ out)
{
    extern __shared__ char smem[];
    const int tid  = threadIdx.x;
    const int wid  = tid >> 5;
    const int lane = tid & 31;
    const int wm = wid >> 1, wn = wid & 1;
    const int n0 = blockIdx.x * BN;
    const int m0 = blockIdx.y * BM;
    const uint32_t sbase = smem_u32(smem);

    // ---- producer addressing: A 512 chunks (2/thread), B 512 chunks (2/thread) ----
    const int rowA = tid >> 2;                 // 0..63 (and +64 for 2nd chunk)
    const int cA   = tid & 3;
    const uint32_t dA0 = (uint32_t)(rowA * 64) + (uint32_t)((cA ^ ((rowA >> 1) & 3)) << 4);
    const int remB = tid & 127;
    const int rowB = remB >> 2;                // 0..31
    const int cB   = remB & 3;
    const int blk0 = tid >> 7;                 // 0..1 (and +2 for 2nd chunk)
    const uint32_t dB0 = (uint32_t)ABYTES + (uint32_t)(blk0 * 2048 + rowB * 64)
                       + (uint32_t)((cB ^ ((rowB >> 1) & 3)) << 4);
    const uint32_t* Arow = g_cvt + OFF_ATT  + (size_t)(m0 + rowA) * 512 + cA * 4;
    const uint32_t* Brow = g_cvt + OFF_WATT + (size_t)(blk0 * 1024 + n0 + rowB) * 512 + cB * 4;

    // ---- consumer (ldsm) addressing, XOR-folded; 64B rows, chunk swizzle ----
    // A frag: matrix = lane>>3: m0 rows+0..7 k0, m1 rows+8 k0, m2 rows+0..7 k8, m3 rows+8 k8
    {
    }
    const int arow = wm * 32 + (((lane >> 3) & 1) << 3) + (lane & 7);
    const int ahi  = (lane >> 4) & 1;          // 16B chunk within k16 step
    const int asx  = (arow >> 1) & 3;
    const uint32_t pA0 = (uint32_t)(arow * 64)
                       + (uint32_t)(((ahi ^ asx) & 1) << 4) + (uint32_t)((asx & 2) << 4);
    const uint32_t pA1 = pA0 + 16 * 64;        // rows +16: same swizzle bits
    // B frag: m0 n+0..7 k0, m1 n+0..7 k8, m2 n+8..15 k0, m3 n+8..15 k8
    const int brow = wn * 16 + (((lane >> 4) & 1) << 3) + (lane & 7);
    const int bhi  = (lane >> 3) & 1;
    const int bsx  = (brow >> 1) & 3;
    const uint32_t pB = (uint32_t)ABYTES + (uint32_t)(brow * 64)
                      + (uint32_t)(((bhi ^ bsx) & 1) << 4) + (uint32_t)((bsx & 2) << 4);

    issue_stage(0, sbase,            dA0, dB0, Arow, Brow);
    issue_stage(1, sbase + BUFB,     dA0, dB0, Arow, Brow);
    issue_stage(2, sbase + 2 * BUFB, dA0, dB0, Arow, Brow);
    issue_stage(3, sbase + 3 * BUFB, dA0, dB0, Arow, Brow);

    int ring_c = 0, ring_i = 4;

    // ===== phase 1: att segment (stages 0..31), 32 accum regs =====
    float ca[2][2][2][4];
    #pragma unroll
    for (int b = 0; b < 2; ++b)
        #pragma unroll
        for (int mf = 0; mf < 2; ++mf)
            #pragma unroll
            for (int nf = 0; nf < 2; ++nf)
                #pragma unroll
                for (int i = 0; i < 4; ++i) ca[b][mf][nf][i] = 0.0f;

    for (int s = 0; s < 32; ++s) {
        cp_wait<3>();
        __syncthreads();
        issue_stage(s + 4, sbase + ring_i * BUFB, dA0, dB0, Arow, Brow);
        compute_stage<2>(sbase + ring_c * BUFB, pA0, pA1, pB, ca);
        ring_c = (ring_c == RING - 1) ? 0 : ring_c + 1;
        ring_i = (ring_i == RING - 1) ? 0 : ring_i + 1;
    }

    // ---- collapse att gates to 16 partials: p = sigmoid(ia) * tanh(aa) ----
    const int gid = lane >> 2, tig = lane & 3;
    float p[2][2][4];
    {
        float bt0[2][2], bt1[2][2];
        #pragma unroll
        for (int nf = 0; nf < 2; ++nf) {
            const int col = n0 + wn * 16 + nf * 8 + tig * 2;
            float2 t0 = __ldg((const float2*)(batt + col));
            float2 t1 = __ldg((const float2*)(batt + 1024 + col));
            bt0[nf][0] = t0.x; bt0[nf][1] = t0.y;
            bt1[nf][0] = t1.x; bt1[nf][1] = t1.y;
        }
        #pragma unroll
        for (int mf = 0; mf < 2; ++mf)
            #pragma unroll
            for (int nf = 0; nf < 2; ++nf)
                #pragma unroll
                for (int i = 0; i < 4; ++i) {
                    const int q = i & 1;
                    float ia = sigmf(ca[0][mf][nf][i] + bt0[nf][q]);
                    float aa = tanhf(ca[1][mf][nf][i] + bt1[nf][q]);
                    p[mf][nf][i] = ia * aa;
                }
    }

    // ===== phase 2: input + hx segments (stages 32..95), 64+16 accum regs =====
    float cm[4][2][2][4];
    #pragma unroll
    for (int b = 0; b < 4; ++b)
        #pragma unroll
        for (int mf = 0; mf < 2; ++mf)
            #pragma unroll
            for (int nf = 0; nf < 2; ++nf)
                #pragma unroll
                for (int i = 0; i < 4; ++i) cm[b][mf][nf][i] = 0.0f;

    for (int s = 32; s < NSTAGE; ++s) {
        cp_wait<3>();
        __syncthreads();
        if (s + 4 < NSTAGE)
            issue_stage(s + 4, sbase + ring_i * BUFB, dA0, dB0, Arow, Brow);
        else
            cp_commit();
        compute_stage<4>(sbase + ring_c * BUFB, pA0, pA1, pB, cm);
        ring_c = (ring_c == RING - 1) ? 0 : ring_c + 1;
        ring_i = (ring_i == RING - 1) ? 0 : ring_i + 1;
    }

    // ---- fused LSTM epilogue ----
    const size_t cy_base = (size_t)BATCH * HDIM;
    #pragma unroll
    for (int mf = 0; mf < 2; ++mf) {
        #pragma unroll
        for (int i2 = 0; i2 < 2; ++i2) {
            const int row = m0 + wm * 32 + mf * 16 + gid + i2 * 8;
            #pragma unroll
            for (int nf = 0; nf < 2; ++nf) {
                const int col = n0 + wn * 16 + nf * 8 + tig * 2;
                float2 cx2 = __ldg((const float2*)(cx + (size_t)row * HDIM + col));
                float hyv[2], cyv[2];
                #pragma unroll
                for (int q = 0; q < 2; ++q) {
                    const int i = i2 * 2 + q;
                    const int n = col + q;
                    float gi  = cm[0][mf][nf][i] + __ldg(bih + n)        + __ldg(bhh + n);
                    float gf  = cm[1][mf][nf][i] + __ldg(bih + 1024 + n) + __ldg(bhh + 1024 + n);
                    float gc  = cm[2][mf][nf][i] + __ldg(bih + 2048 + n) + __ldg(bhh + 2048 + n);
                    float go  = cm[3][mf][nf][i] + __ldg(bih + 3072 + n) + __ldg(bhh + 3072 + n);
                    float i_  = sigmf(gi);
                    float f_  = sigmf(gf);
                    float c_  = tanhf(gc);
                    float o_  = sigmf(go);
                    float cv  = f_ * ((q == 0) ? cx2.x : cx2.y) + i_ * c_ + p[mf][nf][i];
                    cyv[q] = cv;
                    hyv[q] = o_ * tanhf(cv);
                }
                *(float2*)(out + (size_t)row * HDIM + col)           = make_float2(hyv[0], hyv[1]);
                *(float2*)(out + cy_base + (size_t)row * HDIM + col) = make_float2(cyv[0], cyv[1]);
            }
        }
    }
}

extern "C" void kernel_launch(void* const* d_in, const int* in_sizes, int n_in,
                              void* d_out, int out_size)
{
    (void)in_sizes; (void)n_in; (void)out_size;
    const float* inp  = (const float*)d_in[0];
    const float* hx   = (const float*)d_in[1];
    const float* cx   = (const float*)d_in[2];
    const float* att  = (const float*)d_in[3];
    const float* wih  = (const float*)d_in[4];
    const float* whh  = (const float*)d_in[5];
    const float* bih  = (const float*)d_in[6];
    const float* bhh  = (const float*)d_in[7];
    const float* watt = (const float*)d_in[8];
    const float* batt = (const float*)d_in[9];
    float* out = (float*)d_out;

    dim3 cgrid(1024, 6);
    cvt_all_kernel<<<cgrid, 256>>>((const float4*)att, (const float4*)inp,
                                   (const float4*)hx,  (const float4*)watt,
                                   (const float4*)wih, (const float4*)whh);

    cudaFuncSetAttribute(lstm_att_kernel,
                         cudaFuncAttributeMaxDynamicSharedMemorySize, SMEMB);
    dim3 grid(HDIM / BN, BATCH / BM);
    lstm_att_kernel<<<grid, NTH, SMEMB>>>(cx, bih, bhh, batt, out);
}

// round 10
// speedup vs baseline: 1.8466x; 1.1190x over previous
#include <cuda_runtime.h>
#include <cuda_fp16.h>
#include <cstdint>

#define DI __device__ __forceinline__

static constexpr int HDIM   = 1024;
static constexpr int BATCH  = 8192;
static constexpr int BM     = 128;   // batch rows per CTA
static constexpr int BN     = 32;    // gate cols per CTA
static constexpr int NTH    = 256;   // 8 warps: 4 (m) x 2 (n)
static constexpr int NSTAGE = 48;    // 16 att + 16 input + 16 hx K=64-stages
static constexpr int RING   = 3;     // 3-deep ring -> 96KB -> 2 CTAs/SM

// K=64 fp16 stage buffer: A 128x64 (16KB) + B 4x32x64 (16KB); 128B rows
static constexpr int ABYTES = BM * 128;        // 16384
static constexpr int BUFB   = ABYTES + 16384;  // 32768
static constexpr int SMEMB  = RING * BUFB;     // 98304

// fp16 scratch (u32 element offsets; 2 halves per u32)
static constexpr size_t OFF_ATT  = 0;
static constexpr size_t OFF_INP  = 4194304;
static constexpr size_t OFF_HX   = 8388608;
static constexpr size_t OFF_WATT = 12582912;
static constexpr size_t OFF_WIH  = 13631488;
static constexpr size_t OFF_WHH  = 15728640;
static constexpr size_t CVT_TOTAL = 17825792;   // ~71.3 MB

__device__ uint32_t g_cvt[CVT_TOTAL];

DI float sigmf(float x) { return 1.0f / (1.0f + __expf(-x)); }

DI uint32_t smem_u32(const void* p) {
    uint32_t r;
    asm("{ .reg .u64 t; cvta.to.shared.u64 t, %1; cvt.u32.u64 %0, t; }" : "=r"(r) : "l"(p));
    return r;
}
DI void cp16(uint32_t sdst, const uint32_t* gsrc) {
    asm volatile("cp.async.cg.shared.global [%0], [%1], 16;" :: "r"(sdst), "l"(gsrc));
}
DI void cp_commit() { asm volatile("cp.async.commit_group;" ::: "memory"); }
template <int N>
DI void cp_wait() { asm volatile("cp.async.wait_group %0;" :: "n"(N) : "memory"); }

DI void ldsm4(uint32_t* r, uint32_t addr) {
    asm volatile("ldmatrix.sync.aligned.m8n8.x4.shared.b16 {%0,%1,%2,%3}, [%4];"
                 : "=r"(r[0]), "=r"(r[1]), "=r"(r[2]), "=r"(r[3]) : "r"(addr));
}
DI void mma16(float* d, const uint32_t* a, const uint32_t* b) {
    asm volatile(
        "mma.sync.aligned.m16n8k16.row.col.f32.f16.f16.f32 "
        "{%0,%1,%2,%3}, {%4,%5,%6,%7}, {%8,%9}, {%0,%1,%2,%3};"
        : "+f"(d[0]), "+f"(d[1]), "+f"(d[2]), "+f"(d[3])
        : "r"(a[0]), "r"(a[1]), "r"(a[2]), "r"(a[3]), "r"(b[0]), "r"(b[1]));
}

// ---- prepass: fp32 -> fp16(RN) bulk convert, single launch (6 segments) ----
__global__ void cvt_all_kernel(const float4* s_att, const float4* s_inp, const float4* s_hx,
                               const float4* s_watt, const float4* s_wih, const float4* s_whh)
{
    const int seg = blockIdx.y;
    const float4* src;
    uint2* dst;
    int n4;
    uint32_t* g = g_cvt;
    switch (seg) {
        case 0: src = s_att;  dst = (uint2*)(g + OFF_ATT);  n4 = 2097152; break;
        case 1: src = s_inp;  dst = (uint2*)(g + OFF_INP);  n4 = 2097152; break;
        case 2: src = s_hx;   dst = (uint2*)(g + OFF_HX);   n4 = 2097152; break;
        case 3: src = s_watt; dst = (uint2*)(g + OFF_WATT); n4 = 524288;  break;
        case 4: src = s_wih;  dst = (uint2*)(g + OFF_WIH);  n4 = 1048576; break;
        default: src = s_whh; dst = (uint2*)(g + OFF_WHH);  n4 = 1048576; break;
    }
    int i = blockIdx.x * blockDim.x + threadIdx.x;
    int stride = gridDim.x * blockDim.x;
    for (; i < n4; i += stride) {
        float4 v = __ldg(src + i);
        __half2 lo = __float22half2_rn(make_float2(v.x, v.y));
        __half2 hi = __float22half2_rn(make_float2(v.z, v.w));
        dst[i] = make_uint2(*(const uint32_t*)&lo, *(const uint32_t*)&hi);
    }
}

// ---- main kernel ----
// stages 0..15 : A=att,   B=watt (2 att blocks)
// stages 16..31: A=input, B=wih  (4 gate blocks)
// stages 32..47: A=hx,    B=whh  (4 gate blocks)
DI void issue_stage(int s, uint32_t buf, uint32_t sA, uint32_t sB,
                    const uint32_t* Arow, const uint32_t* Brow)
{
    const int seg = s >> 4;
    const int k0  = (s & 15) << 5;                 // u32 offset within 512-u32 row
    const uint32_t bsel = (seg == 0) ? 0u : ((seg == 1) ? 1048576u : 3145728u);
    const uint32_t* Ap = Arow + (size_t)seg * 4194304 + k0;
    const uint32_t* Bp = Brow + bsel + k0;
    const uint32_t dA = buf + sA;
    const uint32_t dB = buf + sB;
    cp16(dA,         Ap);                // rows 0-31
    cp16(dA + 4096,  Ap + 16384);        // rows 32-63
    cp16(dA + 8192,  Ap + 32768);        // rows 64-95
    cp16(dA + 12288, Ap + 49152);        // rows 96-127
    cp16(dB,         Bp);                // gate block 0
    cp16(dB + 4096,  Bp + 524288);       // gate block 1
    if (seg != 0) {
        cp16(dB + 8192,  Bp + 1048576);  // gate block 2
        cp16(dB + 12288, Bp + 1572864);  // gate block 3
    }
    cp_commit();
}

template <int NB>
DI void compute_stage(uint32_t buf, uint32_t pA0, uint32_t pA1, uint32_t pB,
                      float c[][2][2][4])
{
    const uint32_t aA0 = buf + pA0;
    const uint32_t aA1 = buf + pA1;
    const uint32_t bB  = buf + pB;
    #pragma unroll
    for (int k16 = 0; k16 < 4; ++k16) {
        const uint32_t kx = (uint32_t)(k16 << 5);
        uint32_t a0[4], a1[4];
        ldsm4(a0, aA0 ^ kx);
        ldsm4(a1, aA1 ^ kx);
        #pragma unroll
        for (int blk = 0; blk < NB; ++blk) {
            uint32_t b[4];
            ldsm4(b, (bB + blk * 4096) ^ kx);
            mma16(c[blk][0][0], a0, b);
            mma16(c[blk][0][1], a0, b + 2);
            mma16(c[blk][1][0], a1, b);
            mma16(c[blk][1][1], a1, b + 2);
        }
    }
}

__global__ __launch_bounds__(NTH, 2)
void lstm_att_kernel(const float* __restrict__ cx,
                     const float* __restrict__ bih, const float* __restrict__ bhh,
                     const float* __restrict__ batt,
                     float* __restrict__ out)
{
    extern __shared__ char smem[];
    const int tid  = threadIdx.x;
    const int wid  = tid >> 5;
    const int lane = tid & 31;
    const int wm = wid >> 1, wn = wid & 1;
    const int n0 = blockIdx.x * BN;
    const int m0 = blockIdx.y * BM;
    const uint32_t sbase = smem_u32(smem);

    // ---- producer addressing (proven R6 swizzle: 128B rows, chunk ^ row&7) ----
    const int tid8 = tid >> 3;           // 0..31 row within 32-row chunk
    const int cc   = tid & 7;            // 16B chunk
    const uint32_t sw   = (uint32_t)((cc ^ (tid8 & 7)) << 4);
    const uint32_t sAof = (uint32_t)(tid8 * 128) + sw;
    const uint32_t sBof = (uint32_t)ABYTES + (uint32_t)(tid8 * 128) + sw;
    const uint32_t* Arow = g_cvt + OFF_ATT  + (size_t)(m0 + tid8) * 512 + cc * 4;
    const uint32_t* Brow = g_cvt + OFF_WATT + (size_t)(n0 + tid8) * 512 + cc * 4;

    // ---- consumer (ldsm) addressing, XOR-folded ----
    const int arow = wm * 32 + (lane & 15);
    const int ahi  = (lane >> 4) & 1;
    const int ax   = arow & 7;
    const uint32_t pA0 = (uint32_t)(arow * 128)        ^ (uint32_t)(((ahi ^ ax) & 7) << 4);
    const uint32_t pA1 = (uint32_t)((arow + 16) * 128) ^ (uint32_t)(((ahi ^ ax) & 7) << 4);
    const int brow = wn * 16 + (lane & 7) + ((lane & 16) >> 1);
    const int bhi  = (lane >> 3) & 1;
    const int bx   = brow & 7;
    const uint32_t pB  = (uint32_t)ABYTES + ((uint32_t)(brow * 128) ^ (uint32_t)(((bhi ^ bx) & 7) << 4));

    issue_stage(0, sbase,        sAof, sBof, Arow, Brow);
    issue_stage(1, sbase + BUFB, sAof, sBof, Arow, Brow);

    int ring_c = 0, ring_i = 2;

    // ===== phase 1: att segment (stages 0..15), 32 accum regs =====
    float ca[2][2][2][4];
    #pragma unroll
    for (int b = 0; b < 2; ++b)
        #pragma unroll
        for (int mf = 0; mf < 2; ++mf)
            #pragma unroll
            for (int nf = 0; nf < 2; ++nf)
                #pragma unroll
                for (int i = 0; i < 4; ++i) ca[b][mf][nf][i] = 0.0f;

    for (int s = 0; s < 16; ++s) {
        cp_wait<1>();
        __syncthreads();
        issue_stage(s + 2, sbase + ring_i * BUFB, sAof, sBof, Arow, Brow);
        compute_stage<2>(sbase + ring_c * BUFB, pA0, pA1, pB, ca);
        ring_c = (ring_c == RING - 1) ? 0 : ring_c + 1;
        ring_i = (ring_i == RING - 1) ? 0 : ring_i + 1;
    }

    // ---- collapse att gates to 16 partials: p = sigmoid(ia) * tanh(aa) ----
    const int gid = lane >> 2, tig = lane & 3;
    float p[2][2][4];
    {
        float bt0[2][2], bt1[2][2];
        #pragma unroll
        for (int nf = 0; nf < 2; ++nf) {
            const int col = n0 + wn * 16 + nf * 8 + tig * 2;
            float2 t0 = __ldg((const float2*)(batt + col));
            float2 t1 = __ldg((const float2*)(batt + 1024 + col));
            bt0[nf][0] = t0.x; bt0[nf][1] = t0.y;
            bt1[nf][0] = t1.x; bt1[nf][1] = t1.y;
        }
        #pragma unroll
        for (int mf = 0; mf < 2; ++mf)
            #pragma unroll
            for (int nf = 0; nf < 2; ++nf)
                #pragma unroll
                for (int i = 0; i < 4; ++i) {
                    const int q = i & 1;
                    float ia = sigmf(ca[0][mf][nf][i] + bt0[nf][q]);
                    float aa = tanhf(ca[1][mf][nf][i] + bt1[nf][q]);
                    p[mf][nf][i] = ia * aa;
                }
    }

    // ===== phase 2: input + hx segments (stages 16..47), 64+16 accum regs =====
    float cm[4][2][2][4];
    #pragma unroll
    for (int b = 0; b < 4; ++b)
        #pragma unroll
        for (int mf = 0; mf < 2; ++mf)
            #pragma unroll
            for (int nf = 0; nf < 2; ++nf)
                #pragma unroll
                for (int i = 0; i < 4; ++i) cm[b][mf][nf][i] = 0.0f;

    for (int s = 16; s < NSTAGE; ++s) {
        cp_wait<1>();
        __syncthreads();
        if (s + 2 < NSTAGE)
            issue_stage(s + 2, sbase + ring_i * BUFB, sAof, sBof, Arow, Brow);
        else
            cp_commit();
        compute_stage<4>(sbase + ring_c * BUFB, pA0, pA1, pB, cm);
        ring_c = (ring_c == RING - 1) ? 0 : ring_c + 1;
        ring_i = (ring_i == RING - 1) ? 0 : ring_i + 1;
    }

    // ---- fused LSTM epilogue ----
    const size_t cy_base = (size_t)BATCH * HDIM;
    #pragma unroll
    for (int mf = 0; mf < 2; ++mf) {
        #pragma unroll
        for (int i2 = 0; i2 < 2; ++i2) {
            const int row = m0 + wm * 32 + mf * 16 + gid + i2 * 8;
            #pragma unroll
            for (int nf = 0; nf < 2; ++nf) {
                const int col = n0 + wn * 16 + nf * 8 + tig * 2;
                float2 cx2 = __ldg((const float2*)(cx + (size_t)row * HDIM + col));
                float hyv[2], cyv[2];
                #pragma unroll
                for (int q = 0; q < 2; ++q) {
                    const int i = i2 * 2 + q;
                    const int n = col + q;
                    float gi  = cm[0][mf][nf][i] + __ldg(bih + n)        + __ldg(bhh + n);
                    float gf  = cm[1][mf][nf][i] + __ldg(bih + 1024 + n) + __ldg(bhh + 1024 + n);
                    float gc  = cm[2][mf][nf][i] + __ldg(bih + 2048 + n) + __ldg(bhh + 2048 + n);
                    float go  = cm[3][mf][nf][i] + __ldg(bih + 3072 + n) + __ldg(bhh + 3072 + n);
                    float i_  = sigmf(gi);
                    float f_  = sigmf(gf);
                    float c_  = tanhf(gc);
                    float o_  = sigmf(go);
                    float cv  = f_ * ((q == 0) ? cx2.x : cx2.y) + i_ * c_ + p[mf][nf][i];
                    cyv[q] = cv;
                    hyv[q] = o_ * tanhf(cv);
                }
                *(float2*)(out + (size_t)row * HDIM + col)           = make_float2(hyv[0], hyv[1]);
                *(float2*)(out + cy_base + (size_t)row * HDIM + col) = make_float2(cyv[0], cyv[1]);
            }
        }
    }
}

extern "C" void kernel_launch(void* const* d_in, const int* in_sizes, int n_in,
                              void* d_out, int out_size)
{
    (void)in_sizes; (void)n_in; (void)out_size;
    const float* inp  = (const float*)d_in[0];
    const float* hx   = (const float*)d_in[1];
    const float* cx   = (const float*)d_in[2];
    const float* att  = (const float*)d_in[3];
    const float* wih  = (const float*)d_in[4];
    const float* whh  = (const float*)d_in[5];
    const float* bih  = (const float*)d_in[6];
    const float* bhh  = (const float*)d_in[7];
    const float* watt = (const float*)d_in[8];
    const float* batt = (const float*)d_in[9];
    float* out = (float*)d_out;

    dim3 cgrid(1024, 6);
    cvt_all_kernel<<<cgrid, 256>>>((const float4*)att, (const float4*)inp,
                                   (const float4*)hx,  (const float4*)watt,
                                   (const float4*)wih, (const float4*)whh);

    cudaFuncSetAttribute(lstm_att_kernel,
                         cudaFuncAttributeMaxDynamicSharedMemorySize, SMEMB);
    dim3 grid(HDIM / BN, BATCH / BM);
    lstm_att_kernel<<<grid, NTH, SMEMB>>>(cx, bih, bhh, batt, out);
}